// round 6
// baseline (speedup 1.0000x reference)
#include <cuda_runtime.h>
#include <cuda_bf16.h>
#include <math.h>

typedef unsigned long long ull;

#define Bb 32
#define Tt 64
#define Ss 64
#define Ee 256
#define Hh 512
#define Aa 512
#define DVv 32000

// ---------------- device scratch (no allocation allowed) ----------------
__device__ float g_encproj[Bb * Ss * Aa];        // 4 MB
__device__ float g_h0[2][Bb * Hh];
__device__ float g_h1[2][Bb * Hh];
__device__ float g_c0[Bb * Hh];
__device__ float g_c1[Bb * Hh];
__device__ float g_x0[Bb * (Hh + Ee)];
__device__ float g_Hall[Tt * Bb * Hh];           // 4 MB, h1 per step

// ---------------- packed fp32x2 helpers (Blackwell FFMA2) ----------------
__device__ __forceinline__ void ffma2(ull &c, ull a, ull b) {
    asm("fma.rn.f32x2 %0, %1, %2, %0;" : "+l"(c) : "l"(a), "l"(b));
}
__device__ __forceinline__ ull pack2(float x, float y) {
    ull r; asm("mov.b64 %0, {%1, %2};" : "=l"(r) : "f"(x), "f"(y)); return r;
}
__device__ __forceinline__ float2 unpack2(ull v) {
    float2 f; asm("mov.b64 {%0, %1}, %2;" : "=f"(f.x), "=f"(f.y) : "l"(v)); return f;
}

// ---------------- init / tail ----------------
__global__ void init_state(const float* __restrict__ hidden0,
                           const float* __restrict__ cell0) {
    int i = blockIdx.x * 256 + threadIdx.x;
    if (i < Bb * Hh) {
        g_h0[0][i] = hidden0[i];
        g_h1[0][i] = hidden0[Bb * Hh + i];
        g_c0[i]    = cell0[i];
        g_c1[i]    = cell0[Bb * Hh + i];
    }
}

__global__ void write_tail(float* __restrict__ out) {
    int i = blockIdx.x * 256 + threadIdx.x;
    const int fin = (Tt & 1);  // T=64 -> final h lives in buffer 0
    if (i < Bb * Hh) {
        out[i]              = g_h0[fin][i];
        out[Bb * Hh + i]    = g_h1[fin][i];
        out[2 * Bb * Hh + i] = g_c0[i];
        out[3 * Bb * Hh + i] = g_c1[i];
    }
}

// ---------------- generic fp32 SGEMM (BM=64,BN=64,BK=16, 256 thr, 4x4/thr) ----
// MODE 0: C(g_encproj) = Aext(encoder_output) @ Bm(W2) + bias(b2)   M=2048,N=512
// MODE 1: C(out, row-remapped) = g_Hall @ Bm(Wd) + bias(bd)         M=2048,N=32000
template<int MODE, int N>
__global__ __launch_bounds__(256) void sgemm_k(const float* __restrict__ Aext,
                                               const float* __restrict__ Bm,
                                               const float* __restrict__ bias,
                                               float* __restrict__ Cext) {
    constexpr int K = 512;
    const float* Am = (MODE == 0) ? Aext : g_Hall;
    float* Cm = (MODE == 0) ? g_encproj : Cext;

    __shared__ __align__(16) float As[16][64];
    __shared__ __align__(16) float Bs[16][64];

    const int tid = threadIdx.x;
    const int rowbase = blockIdx.y * 64;
    const int colbase = blockIdx.x * 64;

    // loader mapping
    const int lr  = tid >> 2;   // 0..63 A row
    const int lkq = tid & 3;    // k quad for A
    const int lk  = tid >> 4;   // 0..15 B k
    const int lnq = tid & 15;   // n quad for B
    const float* Ap = Am + (size_t)(rowbase + lr) * K + lkq * 4;
    const float* Bp = Bm + (size_t)lk * N + colbase + lnq * 4;

    // compute mapping: 4 rows x 4 cols per thread, acc pairs along M
    const int mt = tid >> 4, nt = tid & 15;
    const int m0 = mt * 4, n0 = nt * 4;

    ull acc[2][4];
#pragma unroll
    for (int i = 0; i < 2; i++)
#pragma unroll
        for (int j = 0; j < 4; j++) acc[i][j] = 0ull;

    for (int kb = 0; kb < K; kb += 16) {
        float4 av = *(const float4*)(Ap + kb);
        float4 bv = *(const float4*)(Bp + (size_t)kb * N);
        __syncthreads();
        As[lkq * 4 + 0][lr] = av.x;
        As[lkq * 4 + 1][lr] = av.y;
        As[lkq * 4 + 2][lr] = av.z;
        As[lkq * 4 + 3][lr] = av.w;
        *(float4*)&Bs[lk][lnq * 4] = bv;
        __syncthreads();
#pragma unroll
        for (int k = 0; k < 16; k++) {
            ulonglong2 ap = *(const ulonglong2*)&As[k][m0];
            float4 b = *(const float4*)&Bs[k][n0];
            ull b0 = pack2(b.x, b.x), b1p = pack2(b.y, b.y);
            ull b2p = pack2(b.z, b.z), b3p = pack2(b.w, b.w);
            ffma2(acc[0][0], ap.x, b0);  ffma2(acc[1][0], ap.y, b0);
            ffma2(acc[0][1], ap.x, b1p); ffma2(acc[1][1], ap.y, b1p);
            ffma2(acc[0][2], ap.x, b2p); ffma2(acc[1][2], ap.y, b2p);
            ffma2(acc[0][3], ap.x, b3p); ffma2(acc[1][3], ap.y, b3p);
        }
    }

#pragma unroll
    for (int j = 0; j < 4; j++) {
        int col = colbase + n0 + j;
        float bj = bias[col];
        float2 v0 = unpack2(acc[0][j]);
        float2 v1 = unpack2(acc[1][j]);
        float vals[4] = {v0.x, v0.y, v1.x, v1.y};
#pragma unroll
        for (int i = 0; i < 4; i++) {
            int r = rowbase + m0 + i;
            // Hall row r = t*B + b  ->  out row = b*T + t
            int orow = (MODE == 1) ? ((r & 31) * Tt + (r >> 5)) : r;
            Cm[(size_t)orow * N + col] = vals[i] + bj;
        }
    }
}

// ---------------- fused Bahdanau attention + input concat (1 block / batch) ----
__global__ __launch_bounds__(512) void attention_step(
    const float* __restrict__ enc, const float* __restrict__ W1,
    const float* __restrict__ b1, const float* __restrict__ V,
    const float* __restrict__ bV, const float* __restrict__ tokens,
    int rp, int t) {
    __shared__ float h1s[Hh], qs[Aa], Vs[Aa];
    __shared__ float qred[4][Aa];
    __shared__ float sc[Ss], at[Ss];

    const int b = blockIdx.x, tid = threadIdx.x;
    const float* H1 = g_h1[rp] + b * Hh;
    h1s[tid] = H1[tid];
    Vs[tid] = V[tid];
    __syncthreads();

    // q = h1 @ W1 : split K into 4 slices (ks), each (group of 128 thr) does 4 cols
    {
        int jq = tid & 127, ks = tid >> 7;
        int j4 = jq * 4;
        float a0 = 0.f, a1 = 0.f, a2 = 0.f, a3 = 0.f;
        int kend = ks * 128 + 128;
#pragma unroll 4
        for (int k = ks * 128; k < kend; k++) {
            float hv = h1s[k];
            float4 wv = *(const float4*)(W1 + (size_t)k * Aa + j4);
            a0 += hv * wv.x; a1 += hv * wv.y; a2 += hv * wv.z; a3 += hv * wv.w;
        }
        qred[ks][j4]     = a0; qred[ks][j4 + 1] = a1;
        qred[ks][j4 + 2] = a2; qred[ks][j4 + 3] = a3;
    }
    __syncthreads();
    qs[tid] = qred[0][tid] + qred[1][tid] + qred[2][tid] + qred[3][tid] + b1[tid];
    __syncthreads();

    // scores[s] = tanh(enc_proj[b,s,:] + q) . V + bV  (warp per score-group)
    const int warp = tid >> 5, lane = tid & 31;
    const float* ep = g_encproj + (size_t)b * Ss * Aa;
    for (int s = warp; s < Ss; s += 16) {
        float p = 0.f;
        const float* eps = ep + s * Aa;
        for (int a0 = lane; a0 < Aa; a0 += 32)
            p += tanhf(eps[a0] + qs[a0]) * Vs[a0];
#pragma unroll
        for (int o = 16; o; o >>= 1) p += __shfl_xor_sync(0xffffffffu, p, o);
        if (lane == 0) sc[s] = p + bV[0];
    }
    __syncthreads();

    // softmax over S=64 by warp 0
    if (warp == 0) {
        float s0 = sc[lane], s1 = sc[lane + 32];
        float mx = fmaxf(s0, s1);
#pragma unroll
        for (int o = 16; o; o >>= 1) mx = fmaxf(mx, __shfl_xor_sync(0xffffffffu, mx, o));
        float e0 = expf(s0 - mx), e1 = expf(s1 - mx);
        float sm = e0 + e1;
#pragma unroll
        for (int o = 16; o; o >>= 1) sm += __shfl_xor_sync(0xffffffffu, sm, o);
        float inv = 1.f / sm;
        at[lane] = e0 * inv;
        at[lane + 32] = e1 * inv;
    }
    __syncthreads();

    // context[d] = sum_s attn[s] * enc[b,s,d] ; write x0 = [context | x_t]
    const float* eb = enc + (size_t)b * Ss * Hh;
    float c = 0.f;
#pragma unroll 8
    for (int s = 0; s < Ss; s++) c += at[s] * eb[s * Hh + tid];
    float* x0 = g_x0 + b * (Hh + Ee);
    x0[tid] = c;
    if (tid < Ee) x0[Hh + tid] = tokens[((size_t)b * Tt + t) * Ee + tid];
}

// ---------------- one LSTM layer step: z = [X|Hprev]@[Wx;Wh]+b, gates, h/c ----
// grid 64 blocks (8 j-cols each => 32 z-cols incl. 4 gates), 128 threads,
// tile 32m x 32n, thread = 4m x 2n, acc pairs along M via FFMA2.
__global__ __launch_bounds__(128) void lstm_step(int layer, int rp, int t,
                                                 const float* __restrict__ Wx,
                                                 const float* __restrict__ Wh,
                                                 const float* __restrict__ bias) {
    const float* X; int KX; const float* Hprev; float* Hout; float* C; float* Hall;
    if (layer == 0) {
        X = g_x0; KX = Hh + Ee;
        Hprev = g_h0[rp]; Hout = g_h0[1 - rp]; C = g_c0; Hall = nullptr;
    } else {
        X = g_h0[1 - rp]; KX = Hh;
        Hprev = g_h1[rp]; Hout = g_h1[1 - rp]; C = g_c1;
        Hall = g_Hall + (size_t)t * Bb * Hh;
    }

    __shared__ __align__(16) float Us[32][32];
    __shared__ __align__(16) float Ws[32][32];
    __shared__ float Zs[32][33];

    const int tid = threadIdx.x;
    const int j0 = blockIdx.x * 8;
    const int np = tid & 15, mq = tid >> 4;
    const int m0 = mq * 4, np2 = np * 2;

    ull a00 = 0ull, a10 = 0ull, a01 = 0ull, a11 = 0ull;
    const int K = KX + Hh;

    for (int kb = 0; kb < K; kb += 32) {
        float4 uv[2], wv[2];
#pragma unroll
        for (int l = 0; l < 2; l++) {
            int slot = tid + l * 128;
            int um = slot >> 3, ukq = slot & 7;
            int kg = kb + ukq * 4;
            const float* src = (kg < KX) ? (X + (size_t)um * KX + kg)
                                         : (Hprev + (size_t)um * Hh + (kg - KX));
            uv[l] = *(const float4*)src;
            int wk = slot >> 3, sub = slot & 7;
            int gate = sub >> 1, half = sub & 1;
            int col = gate * Hh + j0 + half * 4;
            int kg2 = kb + wk;
            const float* wsrc = (kg2 < KX)
                ? (Wx + (size_t)kg2 * (4 * Hh) + col)
                : (Wh + (size_t)(kg2 - KX) * (4 * Hh) + col);
            wv[l] = *(const float4*)wsrc;
        }
        __syncthreads();
#pragma unroll
        for (int l = 0; l < 2; l++) {
            int slot = tid + l * 128;
            int um = slot >> 3, ukq = slot & 7;
            Us[ukq * 4 + 0][um] = uv[l].x;
            Us[ukq * 4 + 1][um] = uv[l].y;
            Us[ukq * 4 + 2][um] = uv[l].z;
            Us[ukq * 4 + 3][um] = uv[l].w;
            int wk = slot >> 3, sub = slot & 7;
            *(float4*)&Ws[wk][sub * 4] = wv[l];
        }
        __syncthreads();
#pragma unroll
        for (int k = 0; k < 32; k++) {
            ulonglong2 ap = *(const ulonglong2*)&Us[k][m0];
            float2 bb = *(const float2*)&Ws[k][np2];
            ull b0 = pack2(bb.x, bb.x), b1p = pack2(bb.y, bb.y);
            ffma2(a00, ap.x, b0);  ffma2(a10, ap.y, b0);
            ffma2(a01, ap.x, b1p); ffma2(a11, ap.y, b1p);
        }
        __syncthreads();
    }

    {   // stage z tile
        float2 v;
        v = unpack2(a00); Zs[m0 + 0][np2] = v.x; Zs[m0 + 1][np2] = v.y;
        v = unpack2(a10); Zs[m0 + 2][np2] = v.x; Zs[m0 + 3][np2] = v.y;
        v = unpack2(a01); Zs[m0 + 0][np2 + 1] = v.x; Zs[m0 + 1][np2 + 1] = v.y;
        v = unpack2(a11); Zs[m0 + 2][np2 + 1] = v.x; Zs[m0 + 3][np2 + 1] = v.y;
    }
    __syncthreads();

    // gates: 32 m x 8 j outputs, 2 per thread
#pragma unroll
    for (int l = 0; l < 2; l++) {
        int idx = tid + l * 128;
        int m = idx >> 3, jl = idx & 7;
        int j = j0 + jl;
        float zi = Zs[m][jl]      + bias[j];
        float zf = Zs[m][8 + jl]  + bias[Hh + j];
        float zg = Zs[m][16 + jl] + bias[2 * Hh + j];
        float zo = Zs[m][24 + jl] + bias[3 * Hh + j];
        float ig = 1.f / (1.f + expf(-zi));
        float fg = 1.f / (1.f + expf(-zf));
        float og = 1.f / (1.f + expf(-zo));
        float cold = C[m * Hh + j];
        float cn = fg * cold + ig * tanhf(zg);
        float hn = og * tanhf(cn);
        C[m * Hh + j] = cn;
        Hout[m * Hh + j] = hn;
        if (Hall) Hall[m * Hh + j] = hn;
    }
}

// ---------------- launch ----------------
extern "C" void kernel_launch(void* const* d_in, const int* in_sizes, int n_in,
                              void* d_out, int out_size) {
    const float* initial_input  = (const float*)d_in[0];
    const float* hidden0        = (const float*)d_in[1];
    const float* cell0          = (const float*)d_in[2];
    const float* encoder_output = (const float*)d_in[3];
    const float* W1 = (const float*)d_in[4];
    const float* b1 = (const float*)d_in[5];
    const float* W2 = (const float*)d_in[6];
    const float* b2 = (const float*)d_in[7];
    const float* V  = (const float*)d_in[8];
    const float* bV = (const float*)d_in[9];
    const float* Wx0 = (const float*)d_in[10];
    const float* Wh0 = (const float*)d_in[11];
    const float* bL0 = (const float*)d_in[12];
    const float* Wx1 = (const float*)d_in[13];
    const float* Wh1 = (const float*)d_in[14];
    const float* bL1 = (const float*)d_in[15];
    const float* Wd  = (const float*)d_in[16];
    const float* bd  = (const float*)d_in[17];
    float* out = (float*)d_out;

    init_state<<<(Bb * Hh + 255) / 256, 256>>>(hidden0, cell0);

    // enc_proj = encoder_output @ W2 + b2   [2048,512]
    sgemm_k<0, Aa><<<dim3(Aa / 64, (Bb * Ss) / 64), 256>>>(
        encoder_output, W2, b2, nullptr);

    for (int t = 0; t < Tt; t++) {
        int rp = t & 1;
        attention_step<<<Bb, 512>>>(encoder_output, W1, b1, V, bV,
                                    initial_input, rp, t);
        lstm_step<<<Hh / 8, 128>>>(0, rp, t, Wx0, Wh0, bL0);
        lstm_step<<<Hh / 8, 128>>>(1, rp, t, Wx1, Wh1, bL1);
    }

    // logits: all steps at once, rows remapped t*B+b -> b*T+t
    sgemm_k<1, DVv><<<dim3(DVv / 64, (Tt * Bb) / 64), 256>>>(
        nullptr, Wd, bd, out);

    long long total = (long long)Bb * Tt * DVv;
    if ((long long)out_size >= total + 4LL * Bb * Hh)
        write_tail<<<(Bb * Hh + 255) / 256, 256>>>(out + total);
}

// round 7
// speedup vs baseline: 1.2831x; 1.2831x over previous
#include <cuda_runtime.h>
#include <cuda_bf16.h>
#include <math.h>

typedef unsigned long long ull;

#define Bb 32
#define Tt 64
#define Ss 64
#define Ee 256
#define Hh 512
#define Aa 512
#define DVv 32000

// ---------------- device scratch (no allocation allowed) ----------------
__device__ float g_encproj[Bb * Ss * Aa];        // 4 MB
__device__ float g_h0[2][Bb * Hh];
__device__ float g_h1[2][Bb * Hh];
__device__ float g_c0[Bb * Hh];
__device__ float g_c1[Bb * Hh];
__device__ float g_x0[Bb * (Hh + Ee)];
__device__ float g_Hall[Tt * Bb * Hh];           // 4 MB, h1 per step
__device__ float g_zpart[8 * Bb * 4 * Hh];       // 2 MB split-K partials

// ---------------- packed fp32x2 helpers (Blackwell FFMA2) ----------------
__device__ __forceinline__ void ffma2(ull &c, ull a, ull b) {
    asm("fma.rn.f32x2 %0, %1, %2, %0;" : "+l"(c) : "l"(a), "l"(b));
}
__device__ __forceinline__ ull pack2(float x, float y) {
    ull r; asm("mov.b64 %0, {%1, %2};" : "=l"(r) : "f"(x), "f"(y)); return r;
}
__device__ __forceinline__ float2 unpack2(ull v) {
    float2 f; asm("mov.b64 {%0, %1}, %2;" : "=f"(f.x), "=f"(f.y) : "l"(v)); return f;
}

// ---------------- init / tail ----------------
__global__ void init_state(const float* __restrict__ hidden0,
                           const float* __restrict__ cell0) {
    int i = blockIdx.x * 256 + threadIdx.x;
    if (i < Bb * Hh) {
        g_h0[0][i] = hidden0[i];
        g_h1[0][i] = hidden0[Bb * Hh + i];
        g_c0[i]    = cell0[i];
        g_c1[i]    = cell0[Bb * Hh + i];
    }
}

__global__ void write_tail(float* __restrict__ out) {
    int i = blockIdx.x * 256 + threadIdx.x;
    const int fin = (Tt & 1);  // T=64 -> final h lives in buffer 0
    if (i < Bb * Hh) {
        out[i]               = g_h0[fin][i];
        out[Bb * Hh + i]     = g_h1[fin][i];
        out[2 * Bb * Hh + i] = g_c0[i];
        out[3 * Bb * Hh + i] = g_c1[i];
    }
}

// ---------------- generic fp32 SGEMM (BM=64,BN=64,BK=16, 256 thr, 4x4/thr) ----
// MODE 0: C(g_encproj) = Aext(encoder_output) @ Bm(W2) + bias(b2)   M=2048,N=512
// MODE 1: C(out, row-remapped) = g_Hall @ Bm(Wd) + bias(bd)         M=2048,N=32000
template<int MODE, int N>
__global__ __launch_bounds__(256) void sgemm_k(const float* __restrict__ Aext,
                                               const float* __restrict__ Bm,
                                               const float* __restrict__ bias,
                                               float* __restrict__ Cext) {
    constexpr int K = 512;
    const float* Am = (MODE == 0) ? Aext : g_Hall;
    float* Cm = (MODE == 0) ? g_encproj : Cext;

    __shared__ __align__(16) float As[16][64];
    __shared__ __align__(16) float Bs[16][64];

    const int tid = threadIdx.x;
    const int rowbase = blockIdx.y * 64;
    const int colbase = blockIdx.x * 64;

    const int lr  = tid >> 2;
    const int lkq = tid & 3;
    const int lk  = tid >> 4;
    const int lnq = tid & 15;
    const float* Ap = Am + (size_t)(rowbase + lr) * K + lkq * 4;
    const float* Bp = Bm + (size_t)lk * N + colbase + lnq * 4;

    const int mt = tid >> 4, nt = tid & 15;
    const int m0 = mt * 4, n0 = nt * 4;

    ull acc[2][4];
#pragma unroll
    for (int i = 0; i < 2; i++)
#pragma unroll
        for (int j = 0; j < 4; j++) acc[i][j] = 0ull;

    for (int kb = 0; kb < K; kb += 16) {
        float4 av = *(const float4*)(Ap + kb);
        float4 bv = *(const float4*)(Bp + (size_t)kb * N);
        __syncthreads();
        As[lkq * 4 + 0][lr] = av.x;
        As[lkq * 4 + 1][lr] = av.y;
        As[lkq * 4 + 2][lr] = av.z;
        As[lkq * 4 + 3][lr] = av.w;
        *(float4*)&Bs[lk][lnq * 4] = bv;
        __syncthreads();
#pragma unroll
        for (int k = 0; k < 16; k++) {
            ulonglong2 ap = *(const ulonglong2*)&As[k][m0];
            float4 b = *(const float4*)&Bs[k][n0];
            ull b0 = pack2(b.x, b.x), b1p = pack2(b.y, b.y);
            ull b2p = pack2(b.z, b.z), b3p = pack2(b.w, b.w);
            ffma2(acc[0][0], ap.x, b0);  ffma2(acc[1][0], ap.y, b0);
            ffma2(acc[0][1], ap.x, b1p); ffma2(acc[1][1], ap.y, b1p);
            ffma2(acc[0][2], ap.x, b2p); ffma2(acc[1][2], ap.y, b2p);
            ffma2(acc[0][3], ap.x, b3p); ffma2(acc[1][3], ap.y, b3p);
        }
    }

#pragma unroll
    for (int j = 0; j < 4; j++) {
        int col = colbase + n0 + j;
        float bj = bias[col];
        float2 v0 = unpack2(acc[0][j]);
        float2 v1 = unpack2(acc[1][j]);
        float vals[4] = {v0.x, v0.y, v1.x, v1.y};
#pragma unroll
        for (int i = 0; i < 4; i++) {
            int r = rowbase + m0 + i;
            int orow = (MODE == 1) ? ((r & 31) * Tt + (r >> 5)) : r;
            Cm[(size_t)orow * N + col] = vals[i] + bj;
        }
    }
}

// ---------------- fused Bahdanau attention + input concat (1 block / batch) ----
__global__ __launch_bounds__(512) void attention_step(
    const float* __restrict__ enc, const float* __restrict__ W1,
    const float* __restrict__ b1, const float* __restrict__ V,
    const float* __restrict__ bV, const float* __restrict__ tokens,
    int rp, int t) {
    __shared__ float h1s[Hh], qs[Aa], Vs[Aa];
    __shared__ float qred[4][Aa];
    __shared__ float sc[Ss], at[Ss];

    const int b = blockIdx.x, tid = threadIdx.x;
    const float* H1 = g_h1[rp] + b * Hh;
    h1s[tid] = H1[tid];
    Vs[tid] = V[tid];
    __syncthreads();

    {
        int jq = tid & 127, ks = tid >> 7;
        int j4 = jq * 4;
        float a0 = 0.f, a1 = 0.f, a2 = 0.f, a3 = 0.f;
        int kend = ks * 128 + 128;
#pragma unroll 4
        for (int k = ks * 128; k < kend; k++) {
            float hv = h1s[k];
            float4 wv = *(const float4*)(W1 + (size_t)k * Aa + j4);
            a0 += hv * wv.x; a1 += hv * wv.y; a2 += hv * wv.z; a3 += hv * wv.w;
        }
        qred[ks][j4]     = a0; qred[ks][j4 + 1] = a1;
        qred[ks][j4 + 2] = a2; qred[ks][j4 + 3] = a3;
    }
    __syncthreads();
    qs[tid] = qred[0][tid] + qred[1][tid] + qred[2][tid] + qred[3][tid] + b1[tid];
    __syncthreads();

    const int warp = tid >> 5, lane = tid & 31;
    const float* ep = g_encproj + (size_t)b * Ss * Aa;
    for (int s = warp; s < Ss; s += 16) {
        float p = 0.f;
        const float* eps = ep + s * Aa;
        for (int a0 = lane; a0 < Aa; a0 += 32)
            p += tanhf(eps[a0] + qs[a0]) * Vs[a0];
#pragma unroll
        for (int o = 16; o; o >>= 1) p += __shfl_xor_sync(0xffffffffu, p, o);
        if (lane == 0) sc[s] = p + bV[0];
    }
    __syncthreads();

    if (warp == 0) {
        float s0 = sc[lane], s1 = sc[lane + 32];
        float mx = fmaxf(s0, s1);
#pragma unroll
        for (int o = 16; o; o >>= 1) mx = fmaxf(mx, __shfl_xor_sync(0xffffffffu, mx, o));
        float e0 = expf(s0 - mx), e1 = expf(s1 - mx);
        float sm = e0 + e1;
#pragma unroll
        for (int o = 16; o; o >>= 1) sm += __shfl_xor_sync(0xffffffffu, sm, o);
        float inv = 1.f / sm;
        at[lane] = e0 * inv;
        at[lane + 32] = e1 * inv;
    }
    __syncthreads();

    const float* eb = enc + (size_t)b * Ss * Hh;
    float c = 0.f;
#pragma unroll 8
    for (int s = 0; s < Ss; s++) c += at[s] * eb[s * Hh + tid];
    float* x0 = g_x0 + b * (Hh + Ee);
    x0[tid] = c;
    if (tid < Ee) x0[Hh + tid] = tokens[((size_t)b * Tt + t) * Ee + tid];
}

// ---------------- LSTM matmul: split-K, chip-filling ----------------
// grid (64 col-blocks, 8 k-splits), 256 threads. Block computes a 32m x 32n
// partial of z = [X|Hprev] @ [Wx;Wh] over its K-chunk, writes g_zpart.
// Inner loop per k: 2x LDS.64 (dup-packed x, broadcast) + 1x coalesced LDG.64
// (natural W column pair) + 2x FFMA2 -> 1.25 instr/MAC, no syncs.
template<int LAYER>
__global__ __launch_bounds__(256) void lstm_mm(int rp,
        const float* __restrict__ Wx, const float* __restrict__ Wh) {
    constexpr int KX  = LAYER ? Hh : (Hh + Ee);   // 512 or 768
    constexpr int CH  = (KX + Hh) / 8;            // 128 or 160
    constexpr int STR = CH + 1;                   // pad for bank spread
    const float* X     = LAYER ? g_h0[1 - rp] : g_x0;
    const float* Hprev = LAYER ? g_h1[rp]     : g_h0[rp];

    __shared__ ull xd[32 * STR];

    const int tid = threadIdx.x;
    const int ksb = blockIdx.y;
    const int k0  = ksb * CH;
    const int c0  = blockIdx.x * 32;

    {   // stage x chunk into smem, pre-duplicated for f32x2
        int m = tid >> 3;
        int part = tid & 7;
        constexpr int PER = CH / 8;               // 16 or 20 (mult of 4)
        int kb = part * PER;
        const float* xrow = X + (size_t)m * KX;
        const float* hrow = Hprev + m * Hh;
        ull* dst = xd + m * STR + kb;
#pragma unroll
        for (int q = 0; q < PER; q += 4) {
            int kg = k0 + kb + q;                 // always 4-aligned; KX 4-aligned
            float4 v = (kg < KX) ? *(const float4*)(xrow + kg)
                                 : *(const float4*)(hrow + (kg - KX));
            dst[q + 0] = pack2(v.x, v.x);
            dst[q + 1] = pack2(v.y, v.y);
            dst[q + 2] = pack2(v.z, v.z);
            dst[q + 3] = pack2(v.w, v.w);
        }
    }
    __syncthreads();

    const int np = tid & 15;         // n-pair within block (2 cols)
    const int ms = tid >> 4;         // m slot: rows ms and ms+16
    const ull* xa = xd + ms * STR;
    const ull* xb = xd + (ms + 16) * STR;
    const int colp = (c0 >> 1) + np; // ull index into 1024-wide pair row

    int split = KX - k0;
    split = split < 0 ? 0 : (split > CH ? CH : split);

    ull acc0 = 0ull, acc1 = 0ull;
    const ull* wp1 = (const ull*)Wx + (size_t)k0 * 1024 + colp;
#pragma unroll 4
    for (int k = 0; k < split; k++) {
        ull w = wp1[(size_t)k * 1024];
        ffma2(acc0, xa[k], w);
        ffma2(acc1, xb[k], w);
    }
    const ull* wp2 = (const ull*)Wh + ((ptrdiff_t)(k0 + split - KX)) * 1024 + colp;
#pragma unroll 4
    for (int k = split; k < CH; k++) {
        ull w = wp2[(size_t)(k - split) * 1024];
        ffma2(acc0, xa[k], w);
        ffma2(acc1, xb[k], w);
    }

    *(ull*)&g_zpart[((ksb * 32 + ms) * 2048) + c0 + 2 * np]      = acc0;
    *(ull*)&g_zpart[((ksb * 32 + ms + 16) * 2048) + c0 + 2 * np] = acc1;
}

// ---------------- gate epilogue: reduce 8 partials, apply LSTM cell ----------
__global__ __launch_bounds__(256) void lstm_gates(int layer, int rp, int t,
        const float* __restrict__ bias) {
    float *C, *Hout, *Hall = nullptr;
    if (layer == 0) { C = g_c0; Hout = g_h0[1 - rp]; }
    else {
        C = g_c1; Hout = g_h1[1 - rp];
        Hall = g_Hall + (size_t)t * Bb * Hh;
    }
    int idx = blockIdx.x * 256 + threadIdx.x;   // m*512 + j
    int m = idx >> 9, j = idx & 511;
    float zi = bias[j], zf = bias[Hh + j];
    float zg = bias[2 * Hh + j], zo = bias[3 * Hh + j];
#pragma unroll
    for (int ksb = 0; ksb < 8; ksb++) {
        const float* zr = g_zpart + (ksb * 32 + m) * 2048;
        zi += zr[j];
        zf += zr[Hh + j];
        zg += zr[2 * Hh + j];
        zo += zr[3 * Hh + j];
    }
    float ig = 1.f / (1.f + expf(-zi));
    float fg = 1.f / (1.f + expf(-zf));
    float og = 1.f / (1.f + expf(-zo));
    float cn = fg * C[idx] + ig * tanhf(zg);
    float hn = og * tanhf(cn);
    C[idx] = cn;
    Hout[idx] = hn;
    if (Hall) Hall[idx] = hn;
}

// ---------------- launch ----------------
extern "C" void kernel_launch(void* const* d_in, const int* in_sizes, int n_in,
                              void* d_out, int out_size) {
    const float* initial_input  = (const float*)d_in[0];
    const float* hidden0        = (const float*)d_in[1];
    const float* cell0          = (const float*)d_in[2];
    const float* encoder_output = (const float*)d_in[3];
    const float* W1 = (const float*)d_in[4];
    const float* b1 = (const float*)d_in[5];
    const float* W2 = (const float*)d_in[6];
    const float* b2 = (const float*)d_in[7];
    const float* V  = (const float*)d_in[8];
    const float* bV = (const float*)d_in[9];
    const float* Wx0 = (const float*)d_in[10];
    const float* Wh0 = (const float*)d_in[11];
    const float* bL0 = (const float*)d_in[12];
    const float* Wx1 = (const float*)d_in[13];
    const float* Wh1 = (const float*)d_in[14];
    const float* bL1 = (const float*)d_in[15];
    const float* Wd  = (const float*)d_in[16];
    const float* bd  = (const float*)d_in[17];
    float* out = (float*)d_out;

    init_state<<<(Bb * Hh + 255) / 256, 256>>>(hidden0, cell0);

    // enc_proj = encoder_output @ W2 + b2   [2048,512]
    sgemm_k<0, Aa><<<dim3(Aa / 64, (Bb * Ss) / 64), 256>>>(
        encoder_output, W2, b2, nullptr);

    for (int t = 0; t < Tt; t++) {
        int rp = t & 1;
        attention_step<<<Bb, 512>>>(encoder_output, W1, b1, V, bV,
                                    initial_input, rp, t);
        lstm_mm<0><<<dim3(64, 8), 256>>>(rp, Wx0, Wh0);
        lstm_gates<<<64, 256>>>(0, rp, t, bL0);
        lstm_mm<1><<<dim3(64, 8), 256>>>(rp, Wx1, Wh1);
        lstm_gates<<<64, 256>>>(1, rp, t, bL1);
    }

    // logits: all steps at once, rows remapped t*B+b -> b*T+t
    sgemm_k<1, DVv><<<dim3(DVv / 64, (Tt * Bb) / 64), 256>>>(
        nullptr, Wd, bd, out);

    long long total = (long long)Bb * Tt * DVv;
    if ((long long)out_size >= total + 4LL * Bb * Hh)
        write_tail<<<(Bb * Hh + 255) / 256, 256>>>(out + total);
}

// round 8
// speedup vs baseline: 1.3882x; 1.0819x over previous
#include <cuda_runtime.h>
#include <cuda_bf16.h>
#include <math.h>

typedef unsigned long long ull;

#define Bb 32
#define Tt 64
#define Ss 64
#define Ee 256
#define Hh 512
#define Aa 512
#define DVv 32000

// ---------------- device scratch (no allocation allowed) ----------------
__device__ float g_encproj[Bb * Ss * Aa];        // 4 MB
__device__ float g_h0[2][Bb * Hh];
__device__ float g_h1[2][Bb * Hh];
__device__ float g_c0[Bb * Hh];
__device__ float g_c1[Bb * Hh];
__device__ float g_x0[Bb * (Hh + Ee)];
__device__ float g_Hall[Tt * Bb * Hh];           // 4 MB, h1 per step
__device__ float g_zpart[8 * Bb * 4 * Hh];       // 2 MB split-K partials
// repacked LSTM weights: per (bx, ksb) tile, [k2][np][2] ull pairs
__device__ ull g_wpk0[64 * 8 * 160 * 16];        // 10.5 MB (K=1280)
__device__ ull g_wpk1[64 * 8 * 128 * 16];        // 8.4 MB  (K=1024)

// ---------------- packed fp32x2 helpers (Blackwell FFMA2) ----------------
__device__ __forceinline__ void ffma2(ull &c, ull a, ull b) {
    asm("fma.rn.f32x2 %0, %1, %2, %0;" : "+l"(c) : "l"(a), "l"(b));
}
__device__ __forceinline__ ull pack2(float x, float y) {
    ull r; asm("mov.b64 %0, {%1, %2};" : "=l"(r) : "f"(x), "f"(y)); return r;
}
__device__ __forceinline__ float2 unpack2(ull v) {
    float2 f; asm("mov.b64 {%0, %1}, %2;" : "=f"(f.x), "=f"(f.y) : "l"(v)); return f;
}
__device__ __forceinline__ float tanh_fast(float x) {
    float y; asm("tanh.approx.f32 %0, %1;" : "=f"(y) : "f"(x)); return y;
}

// ---------------- init / tail ----------------
__global__ void init_state(const float* __restrict__ hidden0,
                           const float* __restrict__ cell0) {
    int i = blockIdx.x * 256 + threadIdx.x;
    if (i < Bb * Hh) {
        g_h0[0][i] = hidden0[i];
        g_h1[0][i] = hidden0[Bb * Hh + i];
        g_c0[i]    = cell0[i];
        g_c1[i]    = cell0[Bb * Hh + i];
    }
}

__global__ void write_tail(float* __restrict__ out) {
    int i = blockIdx.x * 256 + threadIdx.x;
    const int fin = (Tt & 1);  // T=64 -> final h lives in buffer 0
    if (i < Bb * Hh) {
        out[i]               = g_h0[fin][i];
        out[Bb * Hh + i]     = g_h1[fin][i];
        out[2 * Bb * Hh + i] = g_c0[i];
        out[3 * Bb * Hh + i] = g_c1[i];
    }
}

// ---------------- weight repack: [Wx;Wh] -> tile-contiguous pair layout ----
// dest index i (ull units):
//   tile = i / (CH*16), bx = tile/8, ksb = tile%8
//   ti = i % (CH*16);  k2 = ti>>5;  np = (ti&31)>>1;  j = ti&1
//   kg = ksb*CH + 2*k2 + j;  colp = bx*16 + np
template<int LAYER>
__global__ __launch_bounds__(256) void repack_w(const float* __restrict__ Wx,
                                                const float* __restrict__ Wh) {
    constexpr int KX = LAYER ? Hh : (Hh + Ee);
    constexpr int CH = (KX + Hh) / 8;
    ull* dst = LAYER ? g_wpk1 : g_wpk0;
    int i = blockIdx.x * 256 + threadIdx.x;
    int tile = i / (CH * 16);
    int ti   = i % (CH * 16);
    int bx = tile >> 3, ksb = tile & 7;
    int k2 = ti >> 5;
    int np = (ti & 31) >> 1, j = ti & 1;
    int kg = ksb * CH + 2 * k2 + j;
    int colp = bx * 16 + np;
    const ull* src = (kg < KX)
        ? (const ull*)Wx + (size_t)kg * 1024 + colp
        : (const ull*)Wh + (size_t)(kg - KX) * 1024 + colp;
    dst[i] = *src;
}

// ---------------- generic fp32 SGEMM (BM=64,BN=64,BK=16, 256 thr, 4x4/thr) ----
// MODE 0: C(g_encproj) = Aext(encoder_output) @ Bm(W2) + bias(b2)   M=2048,N=512
// MODE 1: C(out, row-remapped) = g_Hall @ Bm(Wd) + bias(bd)         M=2048,N=32000
template<int MODE, int N>
__global__ __launch_bounds__(256) void sgemm_k(const float* __restrict__ Aext,
                                               const float* __restrict__ Bm,
                                               const float* __restrict__ bias,
                                               float* __restrict__ Cext) {
    constexpr int K = 512;
    const float* Am = (MODE == 0) ? Aext : g_Hall;
    float* Cm = (MODE == 0) ? g_encproj : Cext;

    __shared__ __align__(16) float As[16][64];
    __shared__ __align__(16) float Bs[16][64];

    const int tid = threadIdx.x;
    const int rowbase = blockIdx.y * 64;
    const int colbase = blockIdx.x * 64;

    const int lr  = tid >> 2;
    const int lkq = tid & 3;
    const int lk  = tid >> 4;
    const int lnq = tid & 15;
    const float* Ap = Am + (size_t)(rowbase + lr) * K + lkq * 4;
    const float* Bp = Bm + (size_t)lk * N + colbase + lnq * 4;

    const int mt = tid >> 4, nt = tid & 15;
    const int m0 = mt * 4, n0 = nt * 4;

    ull acc[2][4];
#pragma unroll
    for (int i = 0; i < 2; i++)
#pragma unroll
        for (int j = 0; j < 4; j++) acc[i][j] = 0ull;

    for (int kb = 0; kb < K; kb += 16) {
        float4 av = *(const float4*)(Ap + kb);
        float4 bv = *(const float4*)(Bp + (size_t)kb * N);
        __syncthreads();
        As[lkq * 4 + 0][lr] = av.x;
        As[lkq * 4 + 1][lr] = av.y;
        As[lkq * 4 + 2][lr] = av.z;
        As[lkq * 4 + 3][lr] = av.w;
        *(float4*)&Bs[lk][lnq * 4] = bv;
        __syncthreads();
#pragma unroll
        for (int k = 0; k < 16; k++) {
            ulonglong2 ap = *(const ulonglong2*)&As[k][m0];
            float4 b = *(const float4*)&Bs[k][n0];
            ull b0 = pack2(b.x, b.x), b1p = pack2(b.y, b.y);
            ull b2p = pack2(b.z, b.z), b3p = pack2(b.w, b.w);
            ffma2(acc[0][0], ap.x, b0);  ffma2(acc[1][0], ap.y, b0);
            ffma2(acc[0][1], ap.x, b1p); ffma2(acc[1][1], ap.y, b1p);
            ffma2(acc[0][2], ap.x, b2p); ffma2(acc[1][2], ap.y, b2p);
            ffma2(acc[0][3], ap.x, b3p); ffma2(acc[1][3], ap.y, b3p);
        }
    }

#pragma unroll
    for (int j = 0; j < 4; j++) {
        int col = colbase + n0 + j;
        float bj = bias[col];
        float2 v0 = unpack2(acc[0][j]);
        float2 v1 = unpack2(acc[1][j]);
        float vals[4] = {v0.x, v0.y, v1.x, v1.y};
#pragma unroll
        for (int i = 0; i < 4; i++) {
            int r = rowbase + m0 + i;
            int orow = (MODE == 1) ? ((r & 31) * Tt + (r >> 5)) : r;
            Cm[(size_t)orow * N + col] = vals[i] + bj;
        }
    }
}

// ---------------- fused Bahdanau attention + input concat (1 block / batch) ----
__global__ __launch_bounds__(512) void attention_step(
    const float* __restrict__ enc, const float* __restrict__ W1,
    const float* __restrict__ b1, const float* __restrict__ V,
    const float* __restrict__ bV, const float* __restrict__ tokens,
    int rp, int t) {
    __shared__ float h1s[Hh], qs[Aa], Vs[Aa];
    __shared__ float qred[4][Aa];
    __shared__ float sc[Ss], at[Ss];

    const int b = blockIdx.x, tid = threadIdx.x;
    const float* H1 = g_h1[rp] + b * Hh;
    h1s[tid] = H1[tid];
    Vs[tid] = V[tid];
    __syncthreads();

    {
        int jq = tid & 127, ks = tid >> 7;
        int j4 = jq * 4;
        float a0 = 0.f, a1 = 0.f, a2 = 0.f, a3 = 0.f;
        int kend = ks * 128 + 128;
#pragma unroll 4
        for (int k = ks * 128; k < kend; k++) {
            float hv = h1s[k];
            float4 wv = *(const float4*)(W1 + (size_t)k * Aa + j4);
            a0 += hv * wv.x; a1 += hv * wv.y; a2 += hv * wv.z; a3 += hv * wv.w;
        }
        qred[ks][j4]     = a0; qred[ks][j4 + 1] = a1;
        qred[ks][j4 + 2] = a2; qred[ks][j4 + 3] = a3;
    }
    __syncthreads();
    qs[tid] = qred[0][tid] + qred[1][tid] + qred[2][tid] + qred[3][tid] + b1[tid];
    __syncthreads();

    const int warp = tid >> 5, lane = tid & 31;
    const float* ep = g_encproj + (size_t)b * Ss * Aa;
    for (int s = warp; s < Ss; s += 16) {
        float p = 0.f;
        const float* eps = ep + s * Aa;
#pragma unroll 4
        for (int a0 = lane; a0 < Aa; a0 += 32)
            p += tanh_fast(eps[a0] + qs[a0]) * Vs[a0];
#pragma unroll
        for (int o = 16; o; o >>= 1) p += __shfl_xor_sync(0xffffffffu, p, o);
        if (lane == 0) sc[s] = p + bV[0];
    }
    __syncthreads();

    if (warp == 0) {
        float s0 = sc[lane], s1 = sc[lane + 32];
        float mx = fmaxf(s0, s1);
#pragma unroll
        for (int o = 16; o; o >>= 1) mx = fmaxf(mx, __shfl_xor_sync(0xffffffffu, mx, o));
        float e0 = expf(s0 - mx), e1 = expf(s1 - mx);
        float sm = e0 + e1;
#pragma unroll
        for (int o = 16; o; o >>= 1) sm += __shfl_xor_sync(0xffffffffu, sm, o);
        float inv = 1.f / sm;
        at[lane] = e0 * inv;
        at[lane + 32] = e1 * inv;
    }
    __syncthreads();

    const float* eb = enc + (size_t)b * Ss * Hh;
    float c = 0.f;
#pragma unroll 8
    for (int s = 0; s < Ss; s++) c += at[s] * eb[s * Hh + tid];
    float* x0 = g_x0 + b * (Hh + Ee);
    x0[tid] = c;
    if (tid < Ee) x0[Hh + tid] = tokens[((size_t)b * Tt + t) * Ee + tid];
}

// ---------------- LSTM matmul: split-K, repacked weights, chip-filling -------
// grid (64 col-blocks, 8 k-splits), 256 threads. Block computes a 32m x 32n
// partial of z = [X|Hprev] @ [Wx;Wh] over its K-chunk, writes g_zpart.
// Inner loop per 2k: 1 coalesced LDG.128 (tile-contiguous repacked W, L1-hot
// across the block's 8 warps) + 2 broadcast LDS.128 + 4 FFMA2.
template<int LAYER>
__global__ __launch_bounds__(256) void lstm_mm(int rp) {
    constexpr int KX  = LAYER ? Hh : (Hh + Ee);   // 512 or 768
    constexpr int CH  = (KX + Hh) / 8;            // 128 or 160
    constexpr int C2  = CH / 2;
    constexpr int STR = CH + 2;                   // even pad: 16B-aligned rows
    const float* X     = LAYER ? g_h0[1 - rp] : g_x0;
    const float* Hprev = LAYER ? g_h1[rp]     : g_h0[rp];
    const ull* wpk     = LAYER ? g_wpk1       : g_wpk0;

    __shared__ __align__(16) ull xd[32 * STR];

    const int tid = threadIdx.x;
    const int ksb = blockIdx.y;
    const int k0  = ksb * CH;
    const int bx  = blockIdx.x;
    const int c0  = bx * 32;

    {   // stage x chunk into smem, pre-duplicated for f32x2
        int m = tid >> 3;
        int part = tid & 7;
        constexpr int PER = CH / 8;               // 16 or 20 (mult of 4)
        int kb = part * PER;
        const float* xrow = X + (size_t)m * KX;
        const float* hrow = Hprev + m * Hh;
        ull* dst = xd + m * STR + kb;
#pragma unroll
        for (int q = 0; q < PER; q += 4) {
            int kg = k0 + kb + q;                 // 4-aligned; KX 4-aligned
            float4 v = (kg < KX) ? *(const float4*)(xrow + kg)
                                 : *(const float4*)(hrow + (kg - KX));
            dst[q + 0] = pack2(v.x, v.x);
            dst[q + 1] = pack2(v.y, v.y);
            dst[q + 2] = pack2(v.z, v.z);
            dst[q + 3] = pack2(v.w, v.w);
        }
    }
    __syncthreads();

    const int np = tid & 15;         // n-pair (2 cols)
    const int ms = tid >> 4;         // rows ms and ms+16

    const ulonglong2* wp = (const ulonglong2*)(wpk + (size_t)(bx * 8 + ksb) * (CH * 16)) + np;
    const ulonglong2* xap = (const ulonglong2*)(xd + ms * STR);
    const ulonglong2* xbp = (const ulonglong2*)(xd + (ms + 16) * STR);

    ull acc0 = 0ull, acc1 = 0ull;
#pragma unroll 8
    for (int k2 = 0; k2 < C2; k2++) {
        ulonglong2 w = wp[k2 * 16];
        ulonglong2 a = xap[k2];
        ulonglong2 b = xbp[k2];
        ffma2(acc0, a.x, w.x);
        ffma2(acc1, b.x, w.x);
        ffma2(acc0, a.y, w.y);
        ffma2(acc1, b.y, w.y);
    }

    *(ull*)&g_zpart[((ksb * 32 + ms) * 2048) + c0 + 2 * np]      = acc0;
    *(ull*)&g_zpart[((ksb * 32 + ms + 16) * 2048) + c0 + 2 * np] = acc1;
}

// ---------------- gate epilogue: reduce 8 partials, apply LSTM cell ----------
__global__ __launch_bounds__(256) void lstm_gates(int layer, int rp, int t,
        const float* __restrict__ bias) {
    float *C, *Hout, *Hall = nullptr;
    if (layer == 0) { C = g_c0; Hout = g_h0[1 - rp]; }
    else {
        C = g_c1; Hout = g_h1[1 - rp];
        Hall = g_Hall + (size_t)t * Bb * Hh;
    }
    int idx = blockIdx.x * 256 + threadIdx.x;   // m*512 + j
    int m = idx >> 9, j = idx & 511;
    float zi = bias[j], zf = bias[Hh + j];
    float zg = bias[2 * Hh + j], zo = bias[3 * Hh + j];
#pragma unroll
    for (int ksb = 0; ksb < 8; ksb++) {
        const float* zr = g_zpart + (ksb * 32 + m) * 2048;
        zi += zr[j];
        zf += zr[Hh + j];
        zg += zr[2 * Hh + j];
        zo += zr[3 * Hh + j];
    }
    float ig = 1.f / (1.f + expf(-zi));
    float fg = 1.f / (1.f + expf(-zf));
    float og = 1.f / (1.f + expf(-zo));
    float cn = fg * C[idx] + ig * tanhf(zg);
    float hn = og * tanhf(cn);
    C[idx] = cn;
    Hout[idx] = hn;
    if (Hall) Hall[idx] = hn;
}

// ---------------- launch ----------------
extern "C" void kernel_launch(void* const* d_in, const int* in_sizes, int n_in,
                              void* d_out, int out_size) {
    const float* initial_input  = (const float*)d_in[0];
    const float* hidden0        = (const float*)d_in[1];
    const float* cell0          = (const float*)d_in[2];
    const float* encoder_output = (const float*)d_in[3];
    const float* W1 = (const float*)d_in[4];
    const float* b1 = (const float*)d_in[5];
    const float* W2 = (const float*)d_in[6];
    const float* b2 = (const float*)d_in[7];
    const float* V  = (const float*)d_in[8];
    const float* bV = (const float*)d_in[9];
    const float* Wx0 = (const float*)d_in[10];
    const float* Wh0 = (const float*)d_in[11];
    const float* bL0 = (const float*)d_in[12];
    const float* Wx1 = (const float*)d_in[13];
    const float* Wh1 = (const float*)d_in[14];
    const float* bL1 = (const float*)d_in[15];
    const float* Wd  = (const float*)d_in[16];
    const float* bd  = (const float*)d_in[17];
    float* out = (float*)d_out;

    init_state<<<(Bb * Hh + 255) / 256, 256>>>(hidden0, cell0);

    // one-time (per call) weight repacks
    repack_w<0><<<(64 * 8 * 160 * 16) / 256, 256>>>(Wx0, Wh0);
    repack_w<1><<<(64 * 8 * 128 * 16) / 256, 256>>>(Wx1, Wh1);

    // enc_proj = encoder_output @ W2 + b2   [2048,512]
    sgemm_k<0, Aa><<<dim3(Aa / 64, (Bb * Ss) / 64), 256>>>(
        encoder_output, W2, b2, nullptr);

    for (int t = 0; t < Tt; t++) {
        int rp = t & 1;
        attention_step<<<Bb, 512>>>(encoder_output, W1, b1, V, bV,
                                    initial_input, rp, t);
        lstm_mm<0><<<dim3(64, 8), 256>>>(rp);
        lstm_gates<<<64, 256>>>(0, rp, t, bL0);
        lstm_mm<1><<<dim3(64, 8), 256>>>(rp);
        lstm_gates<<<64, 256>>>(1, rp, t, bL1);
    }

    // logits: all steps at once, rows remapped t*B+b -> b*T+t
    sgemm_k<1, DVv><<<dim3(DVv / 64, (Tt * Bb) / 64), 256>>>(
        nullptr, Wd, bd, out);

    long long total = (long long)Bb * Tt * DVv;
    if ((long long)out_size >= total + 4LL * Bb * Hh)
        write_tail<<<(Bb * Hh + 255) / 256, 256>>>(out + total);
}